// round 14
// baseline (speedup 1.0000x reference)
#include <cuda_runtime.h>
#include <cstdint>
#include <cstddef>

// PHMLinear via mma.sync tf32 — barrier-minimized version.
// 16 rows/CTA, 128 threads / 4 warps, 2 m-tiles per warp (R11 shape).
// Only 2 block-level __syncthreads in the whole kernel; all other
// ordering is warp-private (per-warp staging + warp-own smem regions).

__device__ float g_wrrT[128 * 32];   // [o][er], tf32-rounded

__device__ __forceinline__ uint32_t to_tf32(float f) {
    uint32_t r;
    asm("cvt.rna.tf32.f32 %0, %1;" : "=r"(r) : "f"(f));
    return r;
}

__global__ void phm_prep(const float* __restrict__ wrr) {
    int idx = blockIdx.x * blockDim.x + threadIdx.x;
    if (idx < 4096) {
        int o = idx >> 5, er = idx & 31;
        g_wrrT[idx] = __uint_as_float(to_tf32(wrr[er * 128 + o]));
    }
}

__device__ __forceinline__ void mma8(float& d0, float& d1, float& d2, float& d3,
                                     uint32_t a0, uint32_t a1, uint32_t a2, uint32_t a3,
                                     uint32_t b0, uint32_t b1) {
    asm volatile(
        "mma.sync.aligned.m16n8k8.row.col.f32.tf32.tf32.f32 "
        "{%0,%1,%2,%3}, {%4,%5,%6,%7}, {%8,%9}, {%0,%1,%2,%3};"
        : "+f"(d0), "+f"(d1), "+f"(d2), "+f"(d3)
        : "r"(a0), "r"(a1), "r"(a2), "r"(a3), "r"(b0), "r"(b1));
}

__global__ void __launch_bounds__(128)
phm_tc(const float* __restrict__ x,
       const float* __restrict__ wrl,   // [8][128][4]
       const float* __restrict__ wlf,   // [8][8][8]
       float* __restrict__ out,
       int nrows)
{
    // Region A: per-warp x chunk [vrow][36] (warp-own contiguous block)
    //           -> later D_s [t][36] on the SAME warp-own block.
    __shared__ __align__(16) float sA[4608];
    // Region B: WrlT [32 er][128 i pad132] -> (block sync) -> y1T [32 er][vrow pad132]
    __shared__ __align__(16) float sB[4608];
    __shared__ __align__(16) float s_wl[512];   // [e][c][a]

    const int tid  = threadIdx.x;
    const int lane = tid & 31;
    const int wid  = tid >> 5;
    const int g  = lane >> 2;   // mma groupID
    const int tg = lane & 3;    // mma threadID-in-group
    int row0 = blockIdx.x * 16;
    if (row0 >= nrows) return;

    // ---- stage WrlT (tf32) + wl ----
    #pragma unroll
    for (int k = 0; k < 32; k++) {
        int m = tid + 128 * k;                 // [e][i][r] row-major
        int e = m >> 9, i = (m & 511) >> 2, r = m & 3;
        sB[(e * 4 + r) * 132 + i] = __uint_as_float(to_tf32(wrl[m]));
    }
    #pragma unroll
    for (int k = 0; k < 4; k++) {
        int m = tid + 128 * k;                 // [e][a][c]
        int e = m >> 6, a = (m >> 3) & 7, c = m & 7;
        s_wl[e * 64 + c * 8 + a] = wlf[m];
    }
    __syncthreads();   // block sync #1

    const int mbase = wid * 32;                // warp-own vrows [mbase, mbase+32)

    // ---- MMA1: per-warp staging, warp syncs only ----
    float y[2][4][4];
    #pragma unroll
    for (int mt = 0; mt < 2; mt++)
        #pragma unroll
        for (int nt = 0; nt < 4; nt++)
            #pragma unroll
            for (int j = 0; j < 4; j++) y[mt][nt][j] = 0.0f;

    #pragma unroll 1
    for (int kc = 0; kc < 4; kc++) {
        // warp stages its own 32 vrows x 32 i (256 float4, 8 per lane)
        #pragma unroll
        for (int k = 0; k < 8; k++) {
            int f4 = lane + 32 * k;            // 0..255
            int vrow = mbase + (f4 >> 3);
            int i4 = f4 & 7;
            int row = row0 + (vrow >> 3);
            if (row >= nrows) row = nrows - 1;
            float4 v = *(const float4*)(x + (size_t)row * 1024 + (vrow & 7) * 128 + kc * 32 + i4 * 4);
            v.x = __uint_as_float(to_tf32(v.x));
            v.y = __uint_as_float(to_tf32(v.y));
            v.z = __uint_as_float(to_tf32(v.z));
            v.w = __uint_as_float(to_tf32(v.w));
            *(float4*)(sA + vrow * 36 + i4 * 4) = v;
        }
        __syncwarp();
        #pragma unroll
        for (int kt = 0; kt < 4; kt++) {
            uint32_t b[4][2];
            #pragma unroll
            for (int nt = 0; nt < 4; nt++) {
                const float* bb = sB + (nt * 8 + g) * 132 + kc * 32 + kt * 8 + tg;
                b[nt][0] = __float_as_uint(bb[0]);
                b[nt][1] = __float_as_uint(bb[4]);
            }
            #pragma unroll
            for (int mt = 0; mt < 2; mt++) {
                const float* xa = sA + (mbase + mt * 16) * 36 + kt * 8 + tg;
                uint32_t a0 = __float_as_uint(xa[g * 36]);
                uint32_t a1 = __float_as_uint(xa[(g + 8) * 36]);
                uint32_t a2 = __float_as_uint(xa[g * 36 + 4]);
                uint32_t a3 = __float_as_uint(xa[(g + 8) * 36 + 4]);
                #pragma unroll
                for (int nt = 0; nt < 4; nt++)
                    mma8(y[mt][nt][0], y[mt][nt][1], y[mt][nt][2], y[mt][nt][3],
                         a0, a1, a2, a3, b[nt][0], b[nt][1]);
            }
        }
        __syncwarp();   // warp's LDS done before next kc overwrite
    }

    __syncthreads();   // block sync #2: all warps done with WrlT (sB) and MMA1

    // ---- y1T [er][vrow pad132] into region B (warp writes its own columns) ----
    #pragma unroll
    for (int mt = 0; mt < 2; mt++)
        #pragma unroll
        for (int nt = 0; nt < 4; nt++) {
            int vr = mbase + mt * 16 + g;
            int er = nt * 8 + tg * 2;
            sB[er * 132 + vr]           = y[mt][nt][0];
            sB[(er + 1) * 132 + vr]     = y[mt][nt][1];
            sB[er * 132 + vr + 8]       = y[mt][nt][2];
            sB[(er + 1) * 132 + vr + 8] = y[mt][nt][3];
        }
    __syncwarp();

    // ---- Phase B: uu[rp][e]; er = 4e+tg; t = mbase + rp*8 + g (warp-own cols) ----
    uint32_t uu[4][8];
    #pragma unroll
    for (int e = 0; e < 8; e++) {
        int er = 4 * e + tg;
        float4 w0 = *(const float4*)(s_wl + e * 64 + g * 8);
        float4 w1 = *(const float4*)(s_wl + e * 64 + g * 8 + 4);
        #pragma unroll
        for (int rp = 0; rp < 4; rp++) {
            int vb = (wid * 4 + rp) * 8;
            float4 y0 = *(const float4*)(sB + er * 132 + vb);
            float4 y1v = *(const float4*)(sB + er * 132 + vb + 4);
            float u = y0.x * w0.x + y0.y * w0.y + y0.z * w0.z + y0.w * w0.w
                    + y1v.x * w1.x + y1v.y * w1.y + y1v.z * w1.z + y1v.w * w1.w;
            uu[rp][e] = to_tf32(u);
        }
    }

    // ---- MMA2 in 4 N-quarters; B from g_wrrT (L1-hot); D_s on warp-own sA block ----
    #pragma unroll 1
    for (int qn = 0; qn < 4; qn++) {
        float d[2][4][4];
        #pragma unroll
        for (int mt = 0; mt < 2; mt++)
            #pragma unroll
            for (int nl = 0; nl < 4; nl++)
                #pragma unroll
                for (int j = 0; j < 4; j++) d[mt][nl][j] = 0.0f;

        #pragma unroll
        for (int kt = 0; kt < 4; kt++)
            #pragma unroll
            for (int nl = 0; nl < 4; nl++) {
                int o = qn * 32 + nl * 8 + g;
                const float* bb = g_wrrT + o * 32 + kt * 8 + tg;
                uint32_t b0 = __float_as_uint(__ldg(bb));
                uint32_t b1 = __float_as_uint(__ldg(bb + 4));
                #pragma unroll
                for (int mt = 0; mt < 2; mt++)
                    mma8(d[mt][nl][0], d[mt][nl][1], d[mt][nl][2], d[mt][nl][3],
                         uu[2 * mt][2 * kt], uu[2 * mt + 1][2 * kt],
                         uu[2 * mt][2 * kt + 1], uu[2 * mt + 1][2 * kt + 1],
                         b0, b1);
            }

        // D -> D_s[t][oc pad36], t in warp-own [mbase, mbase+32)
        #pragma unroll
        for (int mt = 0; mt < 2; mt++)
            #pragma unroll
            for (int nl = 0; nl < 4; nl++) {
                int t = mbase + mt * 16 + g;
                int oc = nl * 8 + tg * 2;
                sA[t * 36 + oc]           = d[mt][nl][0];
                sA[t * 36 + oc + 1]       = d[mt][nl][1];
                sA[(t + 8) * 36 + oc]     = d[mt][nl][2];
                sA[(t + 8) * 36 + oc + 1] = d[mt][nl][3];
            }
        __syncwarp();

        // warp-own remap: rows r = wid*4 .. wid*4+3 of the CTA tile
        #pragma unroll
        for (int ii = 0; ii < 8; ii++) {
            int f4l = ii * 32 + lane;          // 0..255 within warp's 4 rows
            int r = wid * 4 + (f4l >> 6);
            int rem = f4l & 63;
            int op = rem >> 1, j4 = rem & 1;
            if (row0 + r < nrows) {
                float4 v;
                v.x = sA[(r * 8 + j4 * 4 + 0) * 36 + op];
                v.y = sA[(r * 8 + j4 * 4 + 1) * 36 + op];
                v.z = sA[(r * 8 + j4 * 4 + 2) * 36 + op];
                v.w = sA[(r * 8 + j4 * 4 + 3) * 36 + op];
                *(float4*)(out + (size_t)(row0 + r) * 1024 + qn * 256 + op * 8 + j4 * 4) = v;
            }
        }
        __syncwarp();
    }
}

extern "C" void kernel_launch(void* const* d_in, const int* in_sizes, int n_in,
                              void* d_out, int out_size) {
    const float* x   = (const float*)d_in[0];
    const float* wrl = (const float*)d_in[1];
    const float* wrr = (const float*)d_in[2];
    const float* wlf = (const float*)d_in[3];
    float* out = (float*)d_out;

    int nrows = in_sizes[0] / 1024;          // B*S = 8192
    phm_prep<<<16, 256>>>(wrr);
    int grid = (nrows + 15) / 16;            // 16 rows per CTA
    phm_tc<<<grid, 128>>>(x, wrl, wlf, out, nrows);
}

// round 15
// speedup vs baseline: 1.3743x; 1.3743x over previous
#include <cuda_runtime.h>
#include <cstdint>
#include <cstddef>

// PHMLinear via mma.sync tf32 — R11 structure + direct-STG epilogue +
// per-warp x staging with register prefetch. 3 block barriers total.
// 16 rows/CTA, 128 threads / 4 warps, 2 m-tiles per warp.

__device__ float g_wrrT[128 * 32];   // [o][er], tf32-rounded

__device__ __forceinline__ uint32_t to_tf32(float f) {
    uint32_t r;
    asm("cvt.rna.tf32.f32 %0, %1;" : "=r"(r) : "f"(f));
    return r;
}

__global__ void phm_prep(const float* __restrict__ wrr) {
    int idx = blockIdx.x * blockDim.x + threadIdx.x;
    if (idx < 4096) {
        int o = idx >> 5, er = idx & 31;
        g_wrrT[idx] = __uint_as_float(to_tf32(wrr[er * 128 + o]));
    }
}

__device__ __forceinline__ void mma8(float& d0, float& d1, float& d2, float& d3,
                                     uint32_t a0, uint32_t a1, uint32_t a2, uint32_t a3,
                                     uint32_t b0, uint32_t b1) {
    asm volatile(
        "mma.sync.aligned.m16n8k8.row.col.f32.tf32.tf32.f32 "
        "{%0,%1,%2,%3}, {%4,%5,%6,%7}, {%8,%9}, {%0,%1,%2,%3};"
        : "+f"(d0), "+f"(d1), "+f"(d2), "+f"(d3)
        : "r"(a0), "r"(a1), "r"(a2), "r"(a3), "r"(b0), "r"(b1));
}

__global__ void __launch_bounds__(128)
phm_tc(const float* __restrict__ x,
       const float* __restrict__ wrl,   // [8][128][4]
       const float* __restrict__ wlf,   // [8][8][8]
       float* __restrict__ out,
       int nrows)
{
    // Region A: per-warp x chunk [vrow][36] -> y1T [32 er][128 vrow pad132]
    __shared__ __align__(16) float sA[4608];
    // Region B: WrlT [32 er][128 i pad132] -> WrrT [128 o][32 er pad36]
    __shared__ __align__(16) float sB[4608];
    __shared__ __align__(16) float s_wl[512];   // [e][c][a]

    const int tid  = threadIdx.x;
    const int lane = tid & 31;
    const int wid  = tid >> 5;
    const int g  = lane >> 2;   // mma groupID
    const int tg = lane & 3;    // mma threadID-in-group
    int row0 = blockIdx.x * 16;
    if (row0 >= nrows) return;

    // ---- stage WrlT (tf32) + wl ----
    #pragma unroll
    for (int k = 0; k < 32; k++) {
        int m = tid + 128 * k;                 // [e][i][r] row-major
        int e = m >> 9, i = (m & 511) >> 2, r = m & 3;
        sB[(e * 4 + r) * 132 + i] = __uint_as_float(to_tf32(wrl[m]));
    }
    #pragma unroll
    for (int k = 0; k < 4; k++) {
        int m = tid + 128 * k;                 // [e][a][c]
        int e = m >> 6, a = (m >> 3) & 7, c = m & 7;
        s_wl[e * 64 + c * 8 + a] = wlf[m];
    }
    __syncthreads();   // block sync #1

    const int mbase = wid * 32;                // warp-own vrows [mbase, mbase+32)

    // per-lane global source: 8 float4 per chunk, warp-own rows
    // f4 = lane + 32k -> vrow = mbase + (f4>>3), i4 = f4&7
    const int vrow_l[1] = {0};
    (void)vrow_l;

    // ---- MMA1 with register-prefetched per-warp staging, warp syncs only ----
    float y[2][4][4];
    #pragma unroll
    for (int mt = 0; mt < 2; mt++)
        #pragma unroll
        for (int nt = 0; nt < 4; nt++)
            #pragma unroll
            for (int j = 0; j < 4; j++) y[mt][nt][j] = 0.0f;

    float4 xq[8];
    // prologue: load chunk 0
    #pragma unroll
    for (int k = 0; k < 8; k++) {
        int f4 = lane + 32 * k;
        int vrow = mbase + (f4 >> 3);
        int i4 = f4 & 7;
        int row = row0 + (vrow >> 3);
        if (row >= nrows) row = nrows - 1;
        xq[k] = *(const float4*)(x + (size_t)row * 1024 + (vrow & 7) * 128 + i4 * 4);
    }

    #pragma unroll 1
    for (int kc = 0; kc < 4; kc++) {
        // STS own chunk (cvt to tf32)
        #pragma unroll
        for (int k = 0; k < 8; k++) {
            int f4 = lane + 32 * k;
            int vrow = mbase + (f4 >> 3);
            int i4 = f4 & 7;
            float4 v = xq[k];
            v.x = __uint_as_float(to_tf32(v.x));
            v.y = __uint_as_float(to_tf32(v.y));
            v.z = __uint_as_float(to_tf32(v.z));
            v.w = __uint_as_float(to_tf32(v.w));
            *(float4*)(sA + vrow * 36 + i4 * 4) = v;
        }
        __syncwarp();

        // issue next chunk's loads; they retire under the MMAs below
        if (kc < 3) {
            #pragma unroll
            for (int k = 0; k < 8; k++) {
                int f4 = lane + 32 * k;
                int vrow = mbase + (f4 >> 3);
                int i4 = f4 & 7;
                int row = row0 + (vrow >> 3);
                if (row >= nrows) row = nrows - 1;
                xq[k] = *(const float4*)(x + (size_t)row * 1024 + (vrow & 7) * 128
                                           + (kc + 1) * 32 + i4 * 4);
            }
        }

        #pragma unroll
        for (int kt = 0; kt < 4; kt++) {
            uint32_t b[4][2];
            #pragma unroll
            for (int nt = 0; nt < 4; nt++) {
                const float* bb = sB + (nt * 8 + g) * 132 + kc * 32 + kt * 8 + tg;
                b[nt][0] = __float_as_uint(bb[0]);
                b[nt][1] = __float_as_uint(bb[4]);
            }
            #pragma unroll
            for (int mt = 0; mt < 2; mt++) {
                const float* xa = sA + (mbase + mt * 16) * 36 + kt * 8 + tg;
                uint32_t a0 = __float_as_uint(xa[g * 36]);
                uint32_t a1 = __float_as_uint(xa[(g + 8) * 36]);
                uint32_t a2 = __float_as_uint(xa[g * 36 + 4]);
                uint32_t a3 = __float_as_uint(xa[(g + 8) * 36 + 4]);
                #pragma unroll
                for (int nt = 0; nt < 4; nt++)
                    mma8(y[mt][nt][0], y[mt][nt][1], y[mt][nt][2], y[mt][nt][3],
                         a0, a1, a2, a3, b[nt][0], b[nt][1]);
            }
        }
        __syncwarp();   // warp's LDS of this chunk done before next STS
    }

    __syncthreads();   // block sync #2: all MMA1 done; x regions & WrlT dead

    // ---- y1T [er][vrow pad132] into region A; WrrT [o][er pad36] into region B ----
    #pragma unroll
    for (int mt = 0; mt < 2; mt++)
        #pragma unroll
        for (int nt = 0; nt < 4; nt++) {
            int vr = mbase + mt * 16 + g;
            int er = nt * 8 + tg * 2;
            sA[er * 132 + vr]           = y[mt][nt][0];
            sA[(er + 1) * 132 + vr]     = y[mt][nt][1];
            sA[er * 132 + vr + 8]       = y[mt][nt][2];
            sA[(er + 1) * 132 + vr + 8] = y[mt][nt][3];
        }
    #pragma unroll
    for (int k = 0; k < 8; k++) {
        int f4 = tid + 128 * k;                // 1024 float4
        int o = f4 >> 3, e4 = f4 & 7;
        *(float4*)(sB + o * 36 + e4 * 4) = *(const float4*)(g_wrrT + o * 32 + e4 * 4);
    }
    __syncthreads();   // block sync #3

    // ---- Phase B: uu[rp][e]; er = 4e+tg; t = mbase + rp*8 + g (warp-own cols) ----
    uint32_t uu[4][8];
    #pragma unroll
    for (int e = 0; e < 8; e++) {
        int er = 4 * e + tg;
        float4 w0 = *(const float4*)(s_wl + e * 64 + g * 8);
        float4 w1 = *(const float4*)(s_wl + e * 64 + g * 8 + 4);
        #pragma unroll
        for (int rp = 0; rp < 4; rp++) {
            int vb = (wid * 4 + rp) * 8;
            float4 y0 = *(const float4*)(sA + er * 132 + vb);
            float4 y1v = *(const float4*)(sA + er * 132 + vb + 4);
            float u = y0.x * w0.x + y0.y * w0.y + y0.z * w0.z + y0.w * w0.w
                    + y1v.x * w1.x + y1v.y * w1.y + y1v.z * w1.z + y1v.w * w1.w;
            uu[rp][e] = to_tf32(u);
        }
    }

    // ---- MMA2 (B from smem WrrT) + direct STG epilogue, no barriers ----
    // D mapping: d[mt][nl][{0,1}] -> row wid*4+mt*2,   cols (qn*32+nl*8+2tg+{0,1})*8+g
    //            d[mt][nl][{2,3}] -> row wid*4+mt*2+1, same cols
    #pragma unroll 1
    for (int qn = 0; qn < 4; qn++) {
        float d[2][4][4];
        #pragma unroll
        for (int mt = 0; mt < 2; mt++)
            #pragma unroll
            for (int nl = 0; nl < 4; nl++)
                #pragma unroll
                for (int j = 0; j < 4; j++) d[mt][nl][j] = 0.0f;

        #pragma unroll
        for (int kt = 0; kt < 4; kt++)
            #pragma unroll
            for (int nl = 0; nl < 4; nl++) {
                int o = qn * 32 + nl * 8 + g;
                const float* bb = sB + o * 36 + kt * 8 + tg;
                uint32_t b0 = __float_as_uint(bb[0]);
                uint32_t b1 = __float_as_uint(bb[4]);
                #pragma unroll
                for (int mt = 0; mt < 2; mt++)
                    mma8(d[mt][nl][0], d[mt][nl][1], d[mt][nl][2], d[mt][nl][3],
                         uu[2 * mt][2 * kt], uu[2 * mt + 1][2 * kt],
                         uu[2 * mt][2 * kt + 1], uu[2 * mt + 1][2 * kt + 1],
                         b0, b1);
            }

        #pragma unroll
        for (int mt = 0; mt < 2; mt++) {
            int r0 = wid * 4 + mt * 2;
            bool ok0 = (row0 + r0) < nrows;
            bool ok1 = (row0 + r0 + 1) < nrows;
            float* og0 = out + (size_t)(row0 + r0) * 1024;
            float* og1 = out + (size_t)(row0 + r0 + 1) * 1024;
            #pragma unroll
            for (int nl = 0; nl < 4; nl++) {
                int col = (qn * 32 + nl * 8 + 2 * tg) * 8 + g;
                if (ok0) {
                    og0[col]     = d[mt][nl][0];
                    og0[col + 8] = d[mt][nl][1];
                }
                if (ok1) {
                    og1[col]     = d[mt][nl][2];
                    og1[col + 8] = d[mt][nl][3];
                }
            }
        }
    }
}

extern "C" void kernel_launch(void* const* d_in, const int* in_sizes, int n_in,
                              void* d_out, int out_size) {
    const float* x   = (const float*)d_in[0];
    const float* wrl = (const float*)d_in[1];
    const float* wrr = (const float*)d_in[2];
    const float* wlf = (const float*)d_in[3];
    float* out = (float*)d_out;

    int nrows = in_sizes[0] / 1024;          // B*S = 8192
    phm_prep<<<16, 256>>>(wrr);
    int grid = (nrows + 15) / 16;            // 16 rows per CTA
    phm_tc<<<grid, 128>>>(x, wrl, wlf, out, nrows);
}